// round 4
// baseline (speedup 1.0000x reference)
#include <cuda_runtime.h>
#include <math_constants.h>

#define N_DIM 512

// Device-global min/max scratch (no allocations allowed).
__device__ float g_mn;
__device__ float g_mx;

__global__ void init_minmax_kernel() {
    g_mn = __int_as_float(0x7F800000);   // +inf
    g_mx = __int_as_float(0xFF800000);   // -inf
}

__device__ __forceinline__ void atomicMinF(float* addr, float v) {
    if (v >= 0.0f) atomicMin((int*)addr, __float_as_int(v));
    else           atomicMax((unsigned int*)addr, __float_as_uint(v));
}
__device__ __forceinline__ void atomicMaxF(float* addr, float v) {
    if (v >= 0.0f) atomicMax((int*)addr, __float_as_int(v));
    else           atomicMin((unsigned int*)addr, __float_as_uint(v));
}

__global__ void minmax_kernel(const float4* __restrict__ in, long long n4) {
    float mn =  CUDART_INF_F;
    float mx = -CUDART_INF_F;
    long long stride = (long long)gridDim.x * blockDim.x;
    for (long long i = (long long)blockIdx.x * blockDim.x + threadIdx.x; i < n4; i += stride) {
        float4 v = in[i];
        mn = fminf(mn, fminf(fminf(v.x, v.y), fminf(v.z, v.w)));
        mx = fmaxf(mx, fmaxf(fmaxf(v.x, v.y), fmaxf(v.z, v.w)));
    }
    #pragma unroll
    for (int o = 16; o > 0; o >>= 1) {
        mn = fminf(mn, __shfl_xor_sync(0xFFFFFFFFu, mn, o));
        mx = fmaxf(mx, __shfl_xor_sync(0xFFFFFFFFu, mx, o));
    }
    __shared__ float smn[32], smx[32];
    int warp = threadIdx.x >> 5;
    if ((threadIdx.x & 31) == 0) { smn[warp] = mn; smx[warp] = mx; }
    __syncthreads();
    if (threadIdx.x == 0) {
        int nwarps = (blockDim.x + 31) >> 5;
        float bmn = smn[0], bmx = smx[0];
        for (int i = 1; i < nwarps; i++) {
            bmn = fminf(bmn, smn[i]);
            bmx = fmaxf(bmx, smx[i]);
        }
        atomicMinF(&g_mn, bmn);
        atomicMaxF(&g_mx, bmx);
    }
}

__global__ void recur_kernel(const float* __restrict__ in,
                             const float* __restrict__ alpha,
                             const float* __restrict__ beta,
                             float* __restrict__ out,
                             int rows) {
    int row = blockIdx.x * blockDim.x + threadIdx.x;
    if (row >= rows) return;

    const float mn  = g_mn;
    const float mx  = g_mx;
    const float rng = __fsub_rn(mx, mn);
    const float nb  = -beta[0];
    const float a   = alpha[0];

    const float4* __restrict__ xr = (const float4*)(in  + (size_t)row * N_DIM);
    float4* __restrict__       wr = (float4*)      (out + (size_t)row * N_DIM);

    // XLA-matching arithmetic:
    //   xn = (x - mn) / (mx - mn)               (div.rn)
    //   w' = fma(-b, xn, w + (a / w))           (contracted subtract)
    #define STEP(wv, xv)                                               \
        __fmaf_rn(nb, __fdiv_rn(__fsub_rn((xv), mn), rng),             \
                  __fadd_rn((wv), __fdiv_rn(a, (wv))))

    float w = 1.0f;
    float4 X = xr[0];
    float4 O;
    O.x = 1.0f;
    w = STEP(w, X.x); O.y = w;
    w = STEP(w, X.y); O.z = w;
    w = STEP(w, X.z); O.w = w;
    wr[0] = O;
    float xp = X.w;

    #pragma unroll 4
    for (int kb = 1; kb < N_DIM / 4; kb++) {
        X = xr[kb];
        w = STEP(w, xp);  O.x = w;
        w = STEP(w, X.x); O.y = w;
        w = STEP(w, X.y); O.z = w;
        w = STEP(w, X.z); O.w = w;
        xp = X.w;
        wr[kb] = O;
    }
    #undef STEP
}

extern "C" void kernel_launch(void* const* d_in, const int* in_sizes, int n_in,
                              void* d_out, int out_size) {
    const float* in    = (const float*)d_in[0];
    const float* alpha = (const float*)d_in[1];
    const float* beta  = (const float*)d_in[2];
    float* out = (float*)d_out;

    long long n_elems = (long long)in_sizes[0];
    long long n4 = n_elems / 4;
    int rows = (int)(n_elems / N_DIM);

    init_minmax_kernel<<<1, 1>>>();
    minmax_kernel<<<2048, 256>>>((const float4*)in, n4);

    int threads = 256;
    int blocks = (rows + threads - 1) / threads;
    recur_kernel<<<blocks, threads>>>(in, alpha, beta, out, rows);
}

// round 5
// speedup vs baseline: 1.8681x; 1.8681x over previous
#include <cuda_runtime.h>
#include <math_constants.h>

#define N_DIM 512
#define KCH 32            // k-chunk per tile pass
#define NCHUNK (N_DIM / KCH)
#define PITCH 33          // 32 + 1 padding -> conflict-free both phases
#define WPB 8             // warps per block

// Device-global min/max scratch (no allocations allowed).
__device__ float g_mn;
__device__ float g_mx;

__global__ void init_minmax_kernel() {
    g_mn = __int_as_float(0x7F800000);   // +inf
    g_mx = __int_as_float(0xFF800000);   // -inf
}

__device__ __forceinline__ void atomicMinF(float* addr, float v) {
    if (v >= 0.0f) atomicMin((int*)addr, __float_as_int(v));
    else           atomicMax((unsigned int*)addr, __float_as_uint(v));
}
__device__ __forceinline__ void atomicMaxF(float* addr, float v) {
    if (v >= 0.0f) atomicMax((int*)addr, __float_as_int(v));
    else           atomicMin((unsigned int*)addr, __float_as_uint(v));
}

__global__ void minmax_kernel(const float4* __restrict__ in, long long n4) {
    float mn =  CUDART_INF_F;
    float mx = -CUDART_INF_F;
    long long stride = (long long)gridDim.x * blockDim.x;
    for (long long i = (long long)blockIdx.x * blockDim.x + threadIdx.x; i < n4; i += stride) {
        float4 v = in[i];
        mn = fminf(mn, fminf(fminf(v.x, v.y), fminf(v.z, v.w)));
        mx = fmaxf(mx, fmaxf(fmaxf(v.x, v.y), fmaxf(v.z, v.w)));
    }
    #pragma unroll
    for (int o = 16; o > 0; o >>= 1) {
        mn = fminf(mn, __shfl_xor_sync(0xFFFFFFFFu, mn, o));
        mx = fmaxf(mx, __shfl_xor_sync(0xFFFFFFFFu, mx, o));
    }
    __shared__ float smn[32], smx[32];
    int warp = threadIdx.x >> 5;
    if ((threadIdx.x & 31) == 0) { smn[warp] = mn; smx[warp] = mx; }
    __syncthreads();
    if (threadIdx.x == 0) {
        int nwarps = (blockDim.x + 31) >> 5;
        float bmn = smn[0], bmx = smx[0];
        for (int i = 1; i < nwarps; i++) {
            bmn = fminf(bmn, smn[i]);
            bmx = fmaxf(bmx, smx[i]);
        }
        atomicMinF(&g_mn, bmn);
        atomicMaxF(&g_mx, bmx);
    }
}

// Warp-tiled recurrence: each warp processes 32 rows. k is tiled in chunks of
// KCH. Global loads/stores are lane-per-column (fully coalesced); the serial
// recurrence reads/writes a warp-private smem tile (pitch 33, conflict-free).
// Next chunk's LDGs are pipelined into registers during compute.
__global__ void __launch_bounds__(WPB * 32) recur_kernel(
        const float* __restrict__ in,
        const float* __restrict__ alpha,
        const float* __restrict__ beta,
        float* __restrict__ out,
        int rows) {
    __shared__ float tile_s[WPB][32 * PITCH];

    const int lane = threadIdx.x & 31;
    const int warp = threadIdx.x >> 5;
    const int wgid = blockIdx.x * WPB + warp;
    if (wgid * 32 >= rows) return;

    float* tile = tile_s[warp];

    const float mn  = g_mn;
    const float rng = __fsub_rn(g_mx, mn);
    const float inv = __fdiv_rn(1.0f, rng);   // == div-by-rng bitwise (verified R2/R3)
    const float a   = alpha[0];
    const float nb  = -beta[0];

    const size_t base = (size_t)wgid * 32 * N_DIM;
    const float* __restrict__ inw  = in  + base;
    float* __restrict__       outw = out + base;

    // Prologue: load chunk 0 into registers (coalesced: lane = column).
    float r[32];
    #pragma unroll
    for (int j = 0; j < 32; j++)
        r[j] = inw[(size_t)j * N_DIM + lane];

    float w = 1.0f;

    #pragma unroll 1
    for (int c = 0; c < NCHUNK; c++) {
        // Stage current chunk regs -> smem (transposed write, conflict-free).
        #pragma unroll
        for (int j = 0; j < 32; j++)
            tile[j * PITCH + lane] = r[j];
        __syncwarp();

        // Issue next chunk's loads; they overlap the compute below.
        if (c + 1 < NCHUNK) {
            const int k0n = (c + 1) * KCH;
            #pragma unroll
            for (int j = 0; j < 32; j++)
                r[j] = inw[(size_t)j * N_DIM + k0n + lane];
        }

        // Serial recurrence: lane = row. Read x, overwrite slot with w_k
        // (out[:,k] is the *pre-step* w). Exact XLA arithmetic:
        //   xn = (x - mn) * inv ; w' = fma(-b, xn, w + (a / w))
        #pragma unroll
        for (int kk = 0; kk < KCH; kk++) {
            float x = tile[lane * PITCH + kk];
            tile[lane * PITCH + kk] = w;
            float xn = __fmul_rn(__fsub_rn(x, mn), inv);
            w = __fmaf_rn(nb, xn, __fadd_rn(w, __fdiv_rn(a, w)));
        }
        __syncwarp();

        // Coalesced store of this chunk's w values.
        const int k0 = c * KCH;
        #pragma unroll
        for (int j = 0; j < 32; j++)
            outw[(size_t)j * N_DIM + k0 + lane] = tile[j * PITCH + lane];
        __syncwarp();
    }
}

extern "C" void kernel_launch(void* const* d_in, const int* in_sizes, int n_in,
                              void* d_out, int out_size) {
    const float* in    = (const float*)d_in[0];
    const float* alpha = (const float*)d_in[1];
    const float* beta  = (const float*)d_in[2];
    float* out = (float*)d_out;

    long long n_elems = (long long)in_sizes[0];
    long long n4 = n_elems / 4;
    int rows = (int)(n_elems / N_DIM);

    init_minmax_kernel<<<1, 1>>>();
    minmax_kernel<<<2048, 256>>>((const float4*)in, n4);

    int warps_needed = (rows + 31) / 32;
    int blocks = (warps_needed + WPB - 1) / WPB;
    recur_kernel<<<blocks, WPB * 32>>>(in, alpha, beta, out, rows);
}